// round 11
// baseline (speedup 1.0000x reference)
#include <cuda_runtime.h>
#include <cuda_fp16.h>
#include <cstdint>

#define B_ 8
#define T_ 2048
#define D_ 1024
#define H_ 64
#define M_ (B_ * T_)        // 16384 rows

// ---------------------------------------------------------------------------
// Device scratch
// ---------------------------------------------------------------------------
__device__ uint32_t g_Qh[M_ * 32];                  // packed fp16 Q (pre-scaled)
__device__ uint32_t g_Kh[M_ * 32], g_Kl[M_ * 32];   // packed fp16 hi/lo K
__device__ uint32_t g_Vth[256 * 64 * 32];           // V^T fp16 hi, [tile][dim][keypair]
__device__ uint32_t g_Vtl[256 * 64 * 32];           // V^T fp16 lo

// W transposed, fp16 hi/lo split, packed 2-per-u32 along k
__device__ uint32_t g_Whl[6][64][512];

// Split-KV partials: [b][G(128-row block)][split][row][dim]
__device__ float g_Op[B_][16][4][128][H_];
__device__ float g_Ml[B_][16][4][128][2];

// ---------------------------------------------------------------------------
// Helpers
// ---------------------------------------------------------------------------
__device__ __forceinline__ uint32_t smem_u32(const void* p) {
    uint32_t a;
    asm("{ .reg .u64 t; cvta.to.shared.u64 t, %1; cvt.u32.u64 %0, t; }" : "=r"(a) : "l"(p));
    return a;
}
__device__ __forceinline__ uint32_t packhf(float a, float b) {   // a->lo, b->hi
    __half2 h = __floats2half2_rn(a, b);
    return *reinterpret_cast<uint32_t*>(&h);
}
__device__ __forceinline__ float2 unpackhf(uint32_t p) {
    __half2 h = *reinterpret_cast<__half2*>(&p);
    return __half22float2(h);
}
__device__ __forceinline__ void mma_f16(float* c,
    uint32_t a0, uint32_t a1, uint32_t a2, uint32_t a3, uint32_t b0, uint32_t b1)
{
    asm volatile("mma.sync.aligned.m16n8k16.row.col.f32.f16.f16.f32 "
        "{%0,%1,%2,%3}, {%4,%5,%6,%7}, {%8,%9}, {%0,%1,%2,%3};"
        : "+f"(c[0]), "+f"(c[1]), "+f"(c[2]), "+f"(c[3])
        : "r"(a0), "r"(a1), "r"(a2), "r"(a3), "r"(b0), "r"(b1));
}
__device__ __forceinline__ void cp_async16(uint32_t dst, const void* src) {
    asm volatile("cp.async.cg.shared.global [%0], [%1], 16;" :: "r"(dst), "l"(src) : "memory");
}
#define CP_COMMIT()  asm volatile("cp.async.commit_group;" ::: "memory")
#define CP_WAIT1()   asm volatile("cp.async.wait_group 1;"  ::: "memory")
#define CP_WAIT0()   asm volatile("cp.async.wait_group 0;"  ::: "memory")

// ---------------------------------------------------------------------------
// Kernel 0: transpose + fp16 hi/lo split + pack of the three weight matrices.
// ---------------------------------------------------------------------------
__global__ __launch_bounds__(256) void wsplit_kernel(
    const float* __restrict__ Wq, const float* __restrict__ Wk, const float* __restrict__ Wv)
{
    int idx = blockIdx.x * 256 + threadIdx.x;
    int o  = idx >> 15;
    int n  = (idx >> 9) & 63;
    int kp = idx & 511;
    const float* W = (o == 0) ? Wq : (o == 1) ? Wk : Wv;
    float w0 = W[(2 * kp + 0) * 64 + n];
    float w1 = W[(2 * kp + 1) * 64 + n];
    uint32_t hp = packhf(w0, w1);
    float2 f = unpackhf(hp);
    g_Whl[o][n][kp]     = hp;
    g_Whl[3 + o][n][kp] = packhf(w0 - f.x, w1 - f.y);
}

// ---------------------------------------------------------------------------
// Kernel 1: QKV projection, one CTA per (m-tile, output j).  grid (128, 3),
// block 256, 3 CTAs/SM.  Per-CTA: M=128, N=64 (one output), fp16 asymmetric
// 2-mma split: out = x_f16 * (W_hi + W_lo).
// Stage (u32, 5120): xs [128][20] @0, ws_hi [64][20] @2560, ws_lo @3840.
// V CTAs (j==2) transpose+split V inside the CTA and write g_Vth/g_Vtl.
// ---------------------------------------------------------------------------
#define STAGE_U   5120
#define SMEM_DYN  (2 * STAGE_U * 4)

__global__ __launch_bounds__(256, 3) void qkv_mma_kernel(
    const float* __restrict__ x,
    const float* __restrict__ bq, const float* __restrict__ bk, const float* __restrict__ bv)
{
    extern __shared__ uint32_t sm[];
    __shared__ float sbias[64];

    const int tid  = threadIdx.x;
    const int w    = tid >> 5;
    const int lane = tid & 31;
    const int gid  = lane >> 2;
    const int tg   = lane & 3;
    const int m0   = blockIdx.x * 128;
    const int j    = blockIdx.y;           // 0=Q, 1=K, 2=V

    if (tid < 64)
        sbias[tid] = ((j == 0) ? bq : (j == 1) ? bk : bv)[tid];

    const int xrow  = tid >> 1;            // 0..127
    const int xhalf = tid & 1;
    const float* xbase = x + (size_t)(m0 + xrow) * D_ + xhalf * 16;

    // W cp.async addressing: one hi + one lo 16B segment per thread per chunk
    const int wn = tid >> 2, wg = tid & 3;
    const uint32_t wdst_hi = 2560u + (uint32_t)wn * 20u + (uint32_t)wg * 4u;
    const uint32_t wdst_lo = 3840u + (uint32_t)wn * 20u + (uint32_t)wg * 4u;
    const uint32_t* wsrc_hi = &g_Whl[j][wn][wg * 4];
    const uint32_t* wsrc_lo = &g_Whl[3 + j][wn][wg * 4];
    const uint32_t smbase = smem_u32(sm);

    float acc[8][4];
    #pragma unroll
    for (int nt = 0; nt < 8; nt++)
        #pragma unroll
        for (int i = 0; i < 4; i++) acc[nt][i] = 0.0f;

    cp_async16(smbase + wdst_hi * 4, wsrc_hi);
    cp_async16(smbase + wdst_lo * 4, wsrc_lo);
    CP_COMMIT();

    float4 xv[2][4];
    #pragma unroll
    for (int i = 0; i < 4; i++) xv[0][i] = *(const float4*)(xbase + i * 4);

    #pragma unroll 2
    for (int s = 0; s < 32; s++) {
        const int p   = s & 1;
        const int np  = p ^ 1;
        const uint32_t st = (uint32_t)p * STAGE_U;

        if (s + 1 < 32) {
            cp_async16(smbase + (np * STAGE_U + wdst_hi) * 4, wsrc_hi + (size_t)(s + 1) * 16);
            cp_async16(smbase + (np * STAGE_U + wdst_lo) * 4, wsrc_lo + (size_t)(s + 1) * 16);
        }
        CP_COMMIT();
        if (s + 1 < 32) {
            const float* xp = xbase + (s + 1) * 32;
            #pragma unroll
            for (int i = 0; i < 4; i++) xv[np][i] = *(const float4*)(xp + i * 4);
        }

        // pack + STS x chunk: 16 floats -> 8 u32
        {
            uint32_t hp[8];
            #pragma unroll
            for (int i = 0; i < 4; i++) {
                float4 v = xv[p][i];
                hp[i * 2 + 0] = packhf(v.x, v.y);
                hp[i * 2 + 1] = packhf(v.z, v.w);
            }
            uint32_t* xs = &sm[st + (uint32_t)xrow * 20u + (uint32_t)xhalf * 8u];
            *(uint4*)(xs + 0) = make_uint4(hp[0], hp[1], hp[2], hp[3]);
            *(uint4*)(xs + 4) = make_uint4(hp[4], hp[5], hp[6], hp[7]);
        }

        CP_WAIT1();
        __syncthreads();

        const uint32_t arow = st + (uint32_t)(w * 16 + gid) * 20u;
        #pragma unroll
        for (int kk = 0; kk < 2; kk++) {
            const uint32_t ka = arow + kk * 8 + tg;
            uint32_t a0 = sm[ka];
            uint32_t a1 = sm[ka + 8 * 20];
            uint32_t a2 = sm[ka + 4];
            uint32_t a3 = sm[ka + 8 * 20 + 4];
            #pragma unroll
            for (int nt = 0; nt < 8; nt++) {
                const uint32_t kb = st + 2560u + (uint32_t)(nt * 8 + gid) * 20u + kk * 8 + tg;
                uint32_t bh0 = sm[kb];
                uint32_t bh1 = sm[kb + 4];
                uint32_t bl0 = sm[kb + 1280];
                uint32_t bl1 = sm[kb + 1280 + 4];
                mma_f16(acc[nt], a0, a1, a2, a3, bh0, bh1);
                mma_f16(acc[nt], a0, a1, a2, a3, bl0, bl1);
            }
        }
        __syncthreads();
    }

    // ---- epilogue ----
    const int r0 = m0 + w * 16 + gid;
    if (j < 2) {
        const float scale = (j == 0) ? 0.125f : 1.0f;
        #pragma unroll
        for (int nt = 0; nt < 8; nt++) {
            const int col = nt * 8 + 2 * tg;
            float v00 = (acc[nt][0] + sbias[col])     * scale;
            float v01 = (acc[nt][1] + sbias[col + 1]) * scale;
            float v10 = (acc[nt][2] + sbias[col])     * scale;
            float v11 = (acc[nt][3] + sbias[col + 1]) * scale;
            const int pi = nt * 4 + tg;
            if (j == 0) {
                g_Qh[(size_t)r0 * 32 + pi]       = packhf(v00, v01);
                g_Qh[(size_t)(r0 + 8) * 32 + pi] = packhf(v10, v11);
            } else {
                uint32_t h0 = packhf(v00, v01);
                uint32_t h1 = packhf(v10, v11);
                float2 f0 = unpackhf(h0), f1 = unpackhf(h1);
                g_Kh[(size_t)r0 * 32 + pi]       = h0;
                g_Kh[(size_t)(r0 + 8) * 32 + pi] = h1;
                g_Kl[(size_t)r0 * 32 + pi]       = packhf(v00 - f0.x, v01 - f0.y);
                g_Kl[(size_t)(r0 + 8) * 32 + pi] = packhf(v10 - f1.x, v11 - f1.y);
            }
        }
    } else {
        // V: stage fp32 rows in smem, then transposed fp16 hi/lo split out
        float* vsf = (float*)sm;   // [128 rows][stride 65]
        const int lr = w * 16 + gid;
        #pragma unroll
        for (int nt = 0; nt < 8; nt++) {
            const int col = nt * 8 + 2 * tg;
            vsf[lr * 65 + col]             = acc[nt][0] + sbias[col];
            vsf[lr * 65 + col + 1]         = acc[nt][1] + sbias[col + 1];
            vsf[(lr + 8) * 65 + col]       = acc[nt][2] + sbias[col];
            vsf[(lr + 8) * 65 + col + 1]   = acc[nt][3] + sbias[col + 1];
        }
        __syncthreads();
        const int d  = tid >> 2;
        const int kq = tid & 3;
        #pragma unroll
        for (int half = 0; half < 2; half++) {
            const int bt = (m0 >> 6) + half;          // global 64-row tile idx
            uint32_t* oh = g_Vth + (size_t)bt * 2048 + d * 32;
            uint32_t* ol = g_Vtl + (size_t)bt * 2048 + d * 32;
            #pragma unroll
            for (int jj = 0; jj < 8; jj++) {
                int kp = kq * 8 + jj;
                float v0 = vsf[(half * 64 + 2 * kp) * 65 + d];
                float v1 = vsf[(half * 64 + 2 * kp + 1) * 65 + d];
                uint32_t hp = packhf(v0, v1);
                float2 f = unpackhf(hp);
                oh[kp] = hp;
                ol[kp] = packhf(v0 - f.x, v1 - f.y);
            }
        }
    }
}

// ---------------------------------------------------------------------------
// Kernel 2: split-KV causal flash attention, mma.sync fp16 asymmetric split.
// (unchanged from R10: CTA = 128 q-rows, 8 warps, double-buffered cp.async)
// ---------------------------------------------------------------------------
#define ASTG 9216
#define ATT_SMEM (2 * ASTG * 4)

__global__ __launch_bounds__(256, 2) void attn_split_kernel(float* __restrict__ out)
{
    extern __shared__ uint32_t sa[];

    const int bxr = 39 - (int)blockIdx.x;   // heavy first (LPT)
    const int b   = blockIdx.y;

    int h = 0;
    if (bxr >= 4)  h = 1;
    if (bxr >= 12) h = 2;
    if (bxr >= 24) h = 3;
    const int rem = bxr - 2 * h * (h + 1);
    const int qi  = rem / (h + 1);
    const int s   = rem - qi * (h + 1);
    const int G   = 4 * h + qi;              // 128-row q-block 0..15

    const int tid  = threadIdx.x;
    const int w    = tid >> 5;
    const int lane = tid & 31;
    const int gid  = lane >> 2;
    const int tg   = lane & 3;
    const int r0   = G * 128 + w * 16 + gid;

    uint32_t qh[4][4];
    {
        const uint32_t* qhp = g_Qh + ((size_t)b * T_ + r0) * 32;
        #pragma unroll
        for (int kk = 0; kk < 4; kk++) {
            qh[kk][0] = qhp[kk * 8 + tg];
            qh[kk][1] = qhp[8 * 32 + kk * 8 + tg];
            qh[kk][2] = qhp[kk * 8 + tg + 4];
            qh[kk][3] = qhp[8 * 32 + kk * 8 + tg + 4];
        }
    }

    float o[8][4];
    #pragma unroll
    for (int nt = 0; nt < 8; nt++)
        #pragma unroll
        for (int i = 0; i < 4; i++) o[nt][i] = 0.0f;
    float m0v = -1e30f, m1v = -1e30f, l0 = 0.0f, l1 = 0.0f;

    const uint32_t sab = smem_u32(sa);
    int lrow[2], lgq[2];
    #pragma unroll
    for (int i = 0; i < 2; i++) {
        int c = i * 256 + tid;
        lrow[i] = c >> 3;
        lgq[i]  = c & 7;
    }

    const int t0 = s * 8;
    const int t1 = min(s * 8 + 8, 2 * G + 2);
    const int ntile = t1 - t0;

    {
        const size_t krow = (size_t)b * T_ + t0 * 64;
        const size_t vbs  = ((size_t)b * 32 + t0) * 2048;
        #pragma unroll
        for (int i = 0; i < 2; i++) {
            uint32_t doff = (uint32_t)(lrow[i] * 36 + lgq[i] * 4) * 4;
            uint32_t koff = (krow + lrow[i]) * 32 + lgq[i] * 4;
            uint32_t voff = lrow[i] * 32 + lgq[i] * 4;
            cp_async16(sab + doff,             g_Kh + koff);
            cp_async16(sab + 2304 * 4 + doff,  g_Kl + koff);
            cp_async16(sab + 4608 * 4 + doff,  g_Vth + vbs + voff);
            cp_async16(sab + 6912 * 4 + doff,  g_Vtl + vbs + voff);
        }
        CP_COMMIT();
    }

    for (int ti = 0; ti < ntile; ti++) {
        const int tt = t0 + ti;
        const int p  = ti & 1;
        const uint32_t stp = (uint32_t)p * ASTG;

        if (ti + 1 < ntile) {
            const uint32_t stn = (uint32_t)(p ^ 1) * ASTG * 4;
            const size_t krow = (size_t)b * T_ + (tt + 1) * 64;
            const size_t vbs  = ((size_t)b * 32 + (tt + 1)) * 2048;
            #pragma unroll
            for (int i = 0; i < 2; i++) {
                uint32_t doff = stn + (uint32_t)(lrow[i] * 36 + lgq[i] * 4) * 4;
                uint32_t koff = (krow + lrow[i]) * 32 + lgq[i] * 4;
                uint32_t voff = lrow[i] * 32 + lgq[i] * 4;
                cp_async16(sab + doff,             g_Kh + koff);
                cp_async16(sab + 2304 * 4 + doff,  g_Kl + koff);
                cp_async16(sab + 4608 * 4 + doff,  g_Vth + vbs + voff);
                cp_async16(sab + 6912 * 4 + doff,  g_Vtl + vbs + voff);
            }
            CP_COMMIT();
            CP_WAIT1();
        } else {
            CP_WAIT0();
        }
        __syncthreads();

        float st[8][4];
        #pragma unroll
        for (int nt = 0; nt < 8; nt++)
            #pragma unroll
            for (int i = 0; i < 4; i++) st[nt][i] = 0.0f;

        #pragma unroll
        for (int kk = 0; kk < 4; kk++) {
            #pragma unroll
            for (int nt = 0; nt < 8; nt++) {
                const uint32_t base = stp + (uint32_t)(nt * 8 + gid) * 36u + kk * 8 + tg;
                uint32_t bh0 = sa[base],        bh1 = sa[base + 4];
                uint32_t bl0 = sa[base + 2304], bl1 = sa[base + 2304 + 4];
                mma_f16(st[nt], qh[kk][0], qh[kk][1], qh[kk][2], qh[kk][3], bh0, bh1);
                mma_f16(st[nt], qh[kk][0], qh[kk][1], qh[kk][2], qh[kk][3], bl0, bl1);
            }
        }

        if (tt >= 2 * G) {
            #pragma unroll
            for (int nt = 0; nt < 8; nt++) {
                int c0 = tt * 64 + nt * 8 + 2 * tg;
                if (c0     > r0)     st[nt][0] = -1e30f;
                if (c0 + 1 > r0)     st[nt][1] = -1e30f;
                if (c0     > r0 + 8) st[nt][2] = -1e30f;
                if (c0 + 1 > r0 + 8) st[nt][3] = -1e30f;
            }
        }

        float mn0 = m0v, mn1 = m1v;
        #pragma unroll
        for (int nt = 0; nt < 8; nt++) {
            mn0 = fmaxf(mn0, fmaxf(st[nt][0], st[nt][1]));
            mn1 = fmaxf(mn1, fmaxf(st[nt][2], st[nt][3]));
        }
        mn0 = fmaxf(mn0, __shfl_xor_sync(0xffffffffu, mn0, 1));
        mn0 = fmaxf(mn0, __shfl_xor_sync(0xffffffffu, mn0, 2));
        mn1 = fmaxf(mn1, __shfl_xor_sync(0xffffffffu, mn1, 1));
        mn1 = fmaxf(mn1, __shfl_xor_sync(0xffffffffu, mn1, 2));
        const float a0 = __expf(m0v - mn0);
        const float a1 = __expf(m1v - mn1);
        m0v = mn0; m1v = mn1;
        float rs0 = 0.0f, rs1 = 0.0f;
        #pragma unroll
        for (int nt = 0; nt < 8; nt++) {
            st[nt][0] = __expf(st[nt][0] - mn0);
            st[nt][1] = __expf(st[nt][1] - mn0);
            st[nt][2] = __expf(st[nt][2] - mn1);
            st[nt][3] = __expf(st[nt][3] - mn1);
            rs0 += st[nt][0] + st[nt][1];
            rs1 += st[nt][2] + st[nt][3];
        }
        l0 = l0 * a0 + rs0;
        l1 = l1 * a1 + rs1;
        #pragma unroll
        for (int nt = 0; nt < 8; nt++) {
            o[nt][0] *= a0; o[nt][1] *= a0;
            o[nt][2] *= a1; o[nt][3] *= a1;
        }

        #pragma unroll
        for (int kk = 0; kk < 4; kk++) {
            uint32_t ph[4];
            ph[0] = packhf(st[2 * kk][0],     st[2 * kk][1]);
            ph[1] = packhf(st[2 * kk][2],     st[2 * kk][3]);
            ph[2] = packhf(st[2 * kk + 1][0], st[2 * kk + 1][1]);
            ph[3] = packhf(st[2 * kk + 1][2], st[2 * kk + 1][3]);
            #pragma unroll
            for (int nd = 0; nd < 8; nd++) {
                const uint32_t base = stp + 4608u + (uint32_t)(nd * 8 + gid) * 36u + kk * 8 + tg;
                uint32_t vh0 = sa[base],        vh1 = sa[base + 4];
                uint32_t vl0 = sa[base + 2304], vl1 = sa[base + 2304 + 4];
                mma_f16(o[nd], ph[0], ph[1], ph[2], ph[3], vh0, vh1);
                mma_f16(o[nd], ph[0], ph[1], ph[2], ph[3], vl0, vl1);
            }
        }
        __syncthreads();
    }

    l0 += __shfl_xor_sync(0xffffffffu, l0, 1);
    l0 += __shfl_xor_sync(0xffffffffu, l0, 2);
    l1 += __shfl_xor_sync(0xffffffffu, l1, 1);
    l1 += __shfl_xor_sync(0xffffffffu, l1, 2);

    const int rr = w * 16 + gid;
    if (h == 0) {
        const float i0 = 1.0f / l0, i1 = 1.0f / l1;
        float* o0 = out + ((size_t)b * T_ + G * 128 + rr) * H_;
        float* o1 = out + ((size_t)b * T_ + G * 128 + rr + 8) * H_;
        #pragma unroll
        for (int nt = 0; nt < 8; nt++) {
            const int col = nt * 8 + 2 * tg;
            *(float2*)(o0 + col) = make_float2(o[nt][0] * i0, o[nt][1] * i0);
            *(float2*)(o1 + col) = make_float2(o[nt][2] * i1, o[nt][3] * i1);
        }
    } else {
        float* op0 = &g_Op[b][G][s][rr][0];
        float* op1 = &g_Op[b][G][s][rr + 8][0];
        #pragma unroll
        for (int nt = 0; nt < 8; nt++) {
            const int col = nt * 8 + 2 * tg;
            *(float2*)(op0 + col) = make_float2(o[nt][0], o[nt][1]);
            *(float2*)(op1 + col) = make_float2(o[nt][2], o[nt][3]);
        }
        if (tg == 0) {
            g_Ml[b][G][s][rr][0]     = m0v;
            g_Ml[b][G][s][rr][1]     = l0;
            g_Ml[b][G][s][rr + 8][0] = m1v;
            g_Ml[b][G][s][rr + 8][1] = l1;
        }
    }
}

// ---------------------------------------------------------------------------
// Kernel 3: combine split partials (G >= 4).  (unchanged from R10)
// ---------------------------------------------------------------------------
__global__ __launch_bounds__(256) void attn_combine_kernel(float* __restrict__ out)
{
    const int G    = 4 + (blockIdx.x >> 1);
    const int half = blockIdx.x & 1;
    const int b    = blockIdx.y;
    const int tid  = threadIdx.x;
    const int r    = half * 64 + (tid >> 2);
    const int q4   = tid & 3;
    const int dbase = q4 * 16;
    const int ns   = G / 4 + 1;

    float mv[4], lv[4], wv[4];
    float M = -1e30f;
    for (int i = 0; i < ns; i++) {
        mv[i] = g_Ml[b][G][i][r][0];
        lv[i] = g_Ml[b][G][i][r][1];
        M = fmaxf(M, mv[i]);
    }
    float L = 0.0f;
    for (int i = 0; i < ns; i++) {
        wv[i] = __expf(mv[i] - M);
        L += wv[i] * lv[i];
    }
    const float invL = 1.0f / L;

    float acc[16];
    #pragma unroll
    for (int d = 0; d < 16; d++) acc[d] = 0.0f;

    for (int i = 0; i < ns; i++) {
        const float* op = &g_Op[b][G][i][r][dbase];
        const float wi = wv[i];
        #pragma unroll
        for (int d4 = 0; d4 < 4; d4++) {
            float4 v = *(const float4*)(op + d4 * 4);
            acc[d4 * 4 + 0] += wi * v.x;
            acc[d4 * 4 + 1] += wi * v.y;
            acc[d4 * 4 + 2] += wi * v.z;
            acc[d4 * 4 + 3] += wi * v.w;
        }
    }

    float* orow = out + ((size_t)b * T_ + G * 128 + r) * H_ + dbase;
    #pragma unroll
    for (int d4 = 0; d4 < 4; d4++) {
        float4 v;
        v.x = acc[d4 * 4 + 0] * invL;
        v.y = acc[d4 * 4 + 1] * invL;
        v.z = acc[d4 * 4 + 2] * invL;
        v.w = acc[d4 * 4 + 3] * invL;
        *(float4*)(orow + d4 * 4) = v;
    }
}

// ---------------------------------------------------------------------------
extern "C" void kernel_launch(void* const* d_in, const int* in_sizes, int n_in,
                              void* d_out, int out_size)
{
    const float* x  = (const float*)d_in[0];
    const float* Wq = (const float*)d_in[1];
    const float* bq = (const float*)d_in[2];
    const float* Wk = (const float*)d_in[3];
    const float* bk = (const float*)d_in[4];
    const float* Wv = (const float*)d_in[5];
    const float* bv = (const float*)d_in[6];
    float* out = (float*)d_out;

    cudaFuncSetAttribute(qkv_mma_kernel,
                         cudaFuncAttributeMaxDynamicSharedMemorySize, SMEM_DYN);
    cudaFuncSetAttribute(attn_split_kernel,
                         cudaFuncAttributeMaxDynamicSharedMemorySize, ATT_SMEM);

    wsplit_kernel<<<384, 256>>>(Wq, Wk, Wv);
    qkv_mma_kernel<<<dim3(128, 3), 256, SMEM_DYN>>>(x, bq, bk, bv);
    attn_split_kernel<<<dim3(40, B_), 256, ATT_SMEM>>>(out);
    attn_combine_kernel<<<dim3(24, B_), 256>>>(out);
}

// round 12
// speedup vs baseline: 1.1011x; 1.1011x over previous
#include <cuda_runtime.h>
#include <cuda_fp16.h>
#include <cstdint>

#define B_ 8
#define T_ 2048
#define D_ 1024
#define H_ 64
#define M_ (B_ * T_)        // 16384 rows

// ---------------------------------------------------------------------------
// Device scratch
// ---------------------------------------------------------------------------
__device__ float g_V[M_ * H_];                      // fp32 V (intermediate)
__device__ uint32_t g_Qh[M_ * 32];                  // packed fp16 Q (pre-scaled)
__device__ uint32_t g_Kh[M_ * 32], g_Kl[M_ * 32];   // packed fp16 hi/lo K
__device__ uint32_t g_Vth[256 * 64 * 32];           // V^T fp16 hi, [tile][dim][keypair]
__device__ uint32_t g_Vtl[256 * 64 * 32];           // V^T fp16 lo

// W transposed, fp16 hi/lo split, packed 2-per-u32 along k
__device__ uint32_t g_Whl[6][64][512];

// Split-KV partials: [b][G(128-row block)][split][row][dim]
__device__ float g_Op[B_][16][4][128][H_];
__device__ float g_Ml[B_][16][4][128][2];

// ---------------------------------------------------------------------------
// Helpers
// ---------------------------------------------------------------------------
__device__ __forceinline__ uint32_t smem_u32(const void* p) {
    uint32_t a;
    asm("{ .reg .u64 t; cvta.to.shared.u64 t, %1; cvt.u32.u64 %0, t; }" : "=r"(a) : "l"(p));
    return a;
}
__device__ __forceinline__ uint32_t packhf(float a, float b) {   // a->lo, b->hi
    __half2 h = __floats2half2_rn(a, b);
    return *reinterpret_cast<uint32_t*>(&h);
}
__device__ __forceinline__ float2 unpackhf(uint32_t p) {
    __half2 h = *reinterpret_cast<__half2*>(&p);
    return __half22float2(h);
}
__device__ __forceinline__ void mma_f16(float* c,
    uint32_t a0, uint32_t a1, uint32_t a2, uint32_t a3, uint32_t b0, uint32_t b1)
{
    asm volatile("mma.sync.aligned.m16n8k16.row.col.f32.f16.f16.f32 "
        "{%0,%1,%2,%3}, {%4,%5,%6,%7}, {%8,%9}, {%0,%1,%2,%3};"
        : "+f"(c[0]), "+f"(c[1]), "+f"(c[2]), "+f"(c[3])
        : "r"(a0), "r"(a1), "r"(a2), "r"(a3), "r"(b0), "r"(b1));
}
// one instruction loads 4 m8n8 b16 fragments; lane>>3 = matrix, lane&7 = row
__device__ __forceinline__ void ldsm4(uint32_t* r, uint32_t byte_addr) {
    asm volatile("ldmatrix.sync.aligned.m8n8.x4.shared.b16 {%0,%1,%2,%3}, [%4];"
        : "=r"(r[0]), "=r"(r[1]), "=r"(r[2]), "=r"(r[3]) : "r"(byte_addr));
}
__device__ __forceinline__ void cp_async16(uint32_t dst, const void* src) {
    asm volatile("cp.async.cg.shared.global [%0], [%1], 16;" :: "r"(dst), "l"(src) : "memory");
}
#define CP_COMMIT()  asm volatile("cp.async.commit_group;" ::: "memory")
#define CP_WAIT1()   asm volatile("cp.async.wait_group 1;"  ::: "memory")
#define CP_WAIT0()   asm volatile("cp.async.wait_group 0;"  ::: "memory")

// ---------------------------------------------------------------------------
// Kernel 0: transpose + fp16 hi/lo split + pack of the three weight matrices.
// ---------------------------------------------------------------------------
__global__ __launch_bounds__(256) void wsplit_kernel(
    const float* __restrict__ Wq, const float* __restrict__ Wk, const float* __restrict__ Wv)
{
    int idx = blockIdx.x * 256 + threadIdx.x;
    int o  = idx >> 15;
    int n  = (idx >> 9) & 63;
    int kp = idx & 511;
    const float* W = (o == 0) ? Wq : (o == 1) ? Wk : Wv;
    float w0 = W[(2 * kp + 0) * 64 + n];
    float w1 = W[(2 * kp + 1) * 64 + n];
    uint32_t hp = packhf(w0, w1);
    float2 f = unpackhf(hp);
    g_Whl[o][n][kp]     = hp;
    g_Whl[3 + o][n][kp] = packhf(w0 - f.x, w1 - f.y);
}

// ---------------------------------------------------------------------------
// Kernel 1: fused QKV projection, mma.sync fp16, asymmetric 2-mma split.
// R10 structure (M=128, 128 CTAs x 256 thr); operand loads via ldmatrix.x4.
// Stage (u32): xs [128][20] @0, ws [6][64][20] @2560.
// ---------------------------------------------------------------------------
#define STAGE_U   10240
#define SMEM_DYN  (2 * STAGE_U * 4)

__global__ __launch_bounds__(256, 1) void qkv_mma_kernel(
    const float* __restrict__ x,
    const float* __restrict__ bq, const float* __restrict__ bk, const float* __restrict__ bv)
{
    extern __shared__ uint32_t sm[];
    __shared__ float sbias[3][64];

    const int tid  = threadIdx.x;
    const int w    = tid >> 5;
    const int lane = tid & 31;
    const int gid  = lane >> 2;
    const int tg   = lane & 3;
    const int m0   = blockIdx.x * 128;

    if (tid < 64) {
        sbias[0][tid] = bq[tid];
        sbias[1][tid] = bk[tid];
        sbias[2][tid] = bv[tid];
    }

    const int xrow  = tid >> 1;
    const int xhalf = tid & 1;
    const float* xbase = x + (size_t)(m0 + xrow) * D_ + xhalf * 16;

    uint32_t wdst[6];
    const uint32_t* wsrc[6];
    #pragma unroll
    for (int it = 0; it < 6; it++) {
        int sid = it * 256 + tid;
        int j = sid >> 8, n = (sid >> 2) & 63, gq = sid & 3;
        wdst[it] = 2560u + (uint32_t)j * 1280u + (uint32_t)n * 20u + (uint32_t)gq * 4u;
        wsrc[it] = &g_Whl[j][n][gq * 4];
    }
    const uint32_t smbase = smem_u32(sm);

    // ldmatrix lane offsets (u32 units)
    // A: mats [rows, rows+8, kpair+4, rows+8 & kpair+4]
    const uint32_t aofs = (uint32_t)((w * 16 + (lane & 7) + ((lane >> 3) & 1) * 8) * 20
                                     + (lane >> 4) * 4);
    // B: mats [hi0, hi1(+4), lo0(+3840), lo1(+3844)]
    const uint32_t bofs = (uint32_t)((lane & 7) * 20 + ((lane >> 3) & 1) * 4
                                     + (lane >> 4) * 3840);

    float acc[3][8][4];
    #pragma unroll
    for (int o = 0; o < 3; o++)
        #pragma unroll
        for (int nt = 0; nt < 8; nt++)
            #pragma unroll
            for (int i = 0; i < 4; i++) acc[o][nt][i] = 0.0f;

    #pragma unroll
    for (int it = 0; it < 6; it++)
        cp_async16(smbase + wdst[it] * 4, wsrc[it]);
    CP_COMMIT();

    float4 xv[2][4];
    #pragma unroll
    for (int i = 0; i < 4; i++) xv[0][i] = *(const float4*)(xbase + i * 4);

    #pragma unroll 2
    for (int s = 0; s < 32; s++) {
        const int p   = s & 1;
        const int np  = p ^ 1;
        const uint32_t st = (uint32_t)p * STAGE_U;

        if (s + 1 < 32) {
            #pragma unroll
            for (int it = 0; it < 6; it++)
                cp_async16(smbase + (np * STAGE_U + wdst[it]) * 4,
                           wsrc[it] + (size_t)(s + 1) * 16);
        }
        CP_COMMIT();
        if (s + 1 < 32) {
            const float* xp = xbase + (s + 1) * 32;
            #pragma unroll
            for (int i = 0; i < 4; i++) xv[np][i] = *(const float4*)(xp + i * 4);
        }

        {
            uint32_t hp[8];
            #pragma unroll
            for (int i = 0; i < 4; i++) {
                float4 v = xv[p][i];
                hp[i * 2 + 0] = packhf(v.x, v.y);
                hp[i * 2 + 1] = packhf(v.z, v.w);
            }
            uint32_t* xs = &sm[st + (uint32_t)xrow * 20u + (uint32_t)xhalf * 8u];
            *(uint4*)(xs + 0) = make_uint4(hp[0], hp[1], hp[2], hp[3]);
            *(uint4*)(xs + 4) = make_uint4(hp[4], hp[5], hp[6], hp[7]);
        }

        CP_WAIT1();
        __syncthreads();

        #pragma unroll
        for (int kk = 0; kk < 2; kk++) {
            uint32_t a[4];
            ldsm4(a, smbase + (st + aofs + kk * 8) * 4);
            #pragma unroll
            for (int o = 0; o < 3; o++) {
                #pragma unroll
                for (int nt = 0; nt < 8; nt++) {
                    uint32_t bb[4];
                    ldsm4(bb, smbase + (st + 2560u + (uint32_t)o * 1280u
                                        + (uint32_t)nt * 160u + kk * 8 + bofs) * 4);
                    mma_f16(acc[o][nt], a[0], a[1], a[2], a[3], bb[0], bb[1]);
                    mma_f16(acc[o][nt], a[0], a[1], a[2], a[3], bb[2], bb[3]);
                }
            }
        }
        __syncthreads();
    }

    const int r0 = m0 + w * 16 + gid;
    #pragma unroll
    for (int o = 0; o < 3; o++) {
        const float scale = (o == 0) ? 0.125f : 1.0f;
        #pragma unroll
        for (int nt = 0; nt < 8; nt++) {
            const int col = nt * 8 + 2 * tg;
            float v00 = (acc[o][nt][0] + sbias[o][col])     * scale;
            float v01 = (acc[o][nt][1] + sbias[o][col + 1]) * scale;
            float v10 = (acc[o][nt][2] + sbias[o][col])     * scale;
            float v11 = (acc[o][nt][3] + sbias[o][col + 1]) * scale;
            const int pi = nt * 4 + tg;
            if (o == 2) {
                *(float2*)(g_V + (size_t)r0 * H_ + col)       = make_float2(v00, v01);
                *(float2*)(g_V + (size_t)(r0 + 8) * H_ + col) = make_float2(v10, v11);
            } else if (o == 0) {
                g_Qh[(size_t)r0 * 32 + pi]       = packhf(v00, v01);
                g_Qh[(size_t)(r0 + 8) * 32 + pi] = packhf(v10, v11);
            } else {
                uint32_t h0 = packhf(v00, v01);
                uint32_t h1 = packhf(v10, v11);
                float2 f0 = unpackhf(h0), f1 = unpackhf(h1);
                g_Kh[(size_t)r0 * 32 + pi]       = h0;
                g_Kh[(size_t)(r0 + 8) * 32 + pi] = h1;
                g_Kl[(size_t)r0 * 32 + pi]       = packhf(v00 - f0.x, v01 - f0.y);
                g_Kl[(size_t)(r0 + 8) * 32 + pi] = packhf(v10 - f1.x, v11 - f1.y);
            }
        }
    }
}

// ---------------------------------------------------------------------------
// Kernel 1b: V -> transposed fp16 hi/lo split [tile][dim][keypair].
// ---------------------------------------------------------------------------
__global__ __launch_bounds__(256) void vsplit_kernel()
{
    __shared__ float vs[64][65];
    const int bt  = blockIdx.x;
    const int tid = threadIdx.x;
    const float* base = g_V + (size_t)bt * 64 * 64;

    #pragma unroll
    for (int i = 0; i < 16; i++) {
        int id = i * 256 + tid;
        vs[id >> 6][id & 63] = base[id];
    }
    __syncthreads();

    const int d   = tid >> 2;
    const int kpb = (tid & 3) * 8;
    uint32_t* oh = g_Vth + (size_t)bt * 2048 + d * 32;
    uint32_t* ol = g_Vtl + (size_t)bt * 2048 + d * 32;
    #pragma unroll
    for (int j = 0; j < 8; j++) {
        int kp = kpb + j;
        float v0 = vs[2 * kp][d];
        float v1 = vs[2 * kp + 1][d];
        uint32_t hp = packhf(v0, v1);
        float2 f = unpackhf(hp);
        oh[kp] = hp;
        ol[kp] = packhf(v0 - f.x, v1 - f.y);
    }
}

// ---------------------------------------------------------------------------
// Kernel 2: split-KV causal flash attention, mma.sync fp16 asymmetric split.
// R10 structure (CTA = 128 q-rows, 8 warps, double-buffered cp.async);
// K/V operand loads via ldmatrix.x4.
// Stage layout (u32, stride 9216): KH @0, KL @2304, VH @4608, VL @6912.
// ---------------------------------------------------------------------------
#define ASTG 9216
#define ATT_SMEM (2 * ASTG * 4)

__global__ __launch_bounds__(256, 2) void attn_split_kernel(float* __restrict__ out)
{
    extern __shared__ uint32_t sa[];

    const int bxr = 39 - (int)blockIdx.x;   // heavy first (LPT)
    const int b   = blockIdx.y;

    int h = 0;
    if (bxr >= 4)  h = 1;
    if (bxr >= 12) h = 2;
    if (bxr >= 24) h = 3;
    const int rem = bxr - 2 * h * (h + 1);
    const int qi  = rem / (h + 1);
    const int s   = rem - qi * (h + 1);
    const int G   = 4 * h + qi;              // 128-row q-block 0..15

    const int tid  = threadIdx.x;
    const int w    = tid >> 5;
    const int lane = tid & 31;
    const int gid  = lane >> 2;
    const int tg   = lane & 3;
    const int r0   = G * 128 + w * 16 + gid;

    // ldmatrix lane offset: mats [hi0, hi1(+4), lo0(+2304), lo1(+2308)]
    const uint32_t bofs = (uint32_t)((lane & 7) * 36 + ((lane >> 3) & 1) * 4
                                     + (lane >> 4) * 2304);

    uint32_t qh[4][4];
    {
        const uint32_t* qhp = g_Qh + ((size_t)b * T_ + r0) * 32;
        #pragma unroll
        for (int kk = 0; kk < 4; kk++) {
            qh[kk][0] = qhp[kk * 8 + tg];
            qh[kk][1] = qhp[8 * 32 + kk * 8 + tg];
            qh[kk][2] = qhp[kk * 8 + tg + 4];
            qh[kk][3] = qhp[8 * 32 + kk * 8 + tg + 4];
        }
    }

    float o[8][4];
    #pragma unroll
    for (int nt = 0; nt < 8; nt++)
        #pragma unroll
        for (int i = 0; i < 4; i++) o[nt][i] = 0.0f;
    float m0v = -1e30f, m1v = -1e30f, l0 = 0.0f, l1 = 0.0f;

    const uint32_t sab = smem_u32(sa);
    int lrow[2], lgq[2];
    #pragma unroll
    for (int i = 0; i < 2; i++) {
        int c = i * 256 + tid;
        lrow[i] = c >> 3;
        lgq[i]  = c & 7;
    }

    const int t0 = s * 8;
    const int t1 = min(s * 8 + 8, 2 * G + 2);
    const int ntile = t1 - t0;

    {
        const size_t krow = (size_t)b * T_ + t0 * 64;
        const size_t vbs  = ((size_t)b * 32 + t0) * 2048;
        #pragma unroll
        for (int i = 0; i < 2; i++) {
            uint32_t doff = (uint32_t)(lrow[i] * 36 + lgq[i] * 4) * 4;
            uint32_t koff = (krow + lrow[i]) * 32 + lgq[i] * 4;
            uint32_t voff = lrow[i] * 32 + lgq[i] * 4;
            cp_async16(sab + doff,             g_Kh + koff);
            cp_async16(sab + 2304 * 4 + doff,  g_Kl + koff);
            cp_async16(sab + 4608 * 4 + doff,  g_Vth + vbs + voff);
            cp_async16(sab + 6912 * 4 + doff,  g_Vtl + vbs + voff);
        }
        CP_COMMIT();
    }

    for (int ti = 0; ti < ntile; ti++) {
        const int tt = t0 + ti;
        const int p  = ti & 1;
        const uint32_t stp = (uint32_t)p * ASTG;

        if (ti + 1 < ntile) {
            const uint32_t stn = (uint32_t)(p ^ 1) * ASTG * 4;
            const size_t krow = (size_t)b * T_ + (tt + 1) * 64;
            const size_t vbs  = ((size_t)b * 32 + (tt + 1)) * 2048;
            #pragma unroll
            for (int i = 0; i < 2; i++) {
                uint32_t doff = stn + (uint32_t)(lrow[i] * 36 + lgq[i] * 4) * 4;
                uint32_t koff = (krow + lrow[i]) * 32 + lgq[i] * 4;
                uint32_t voff = lrow[i] * 32 + lgq[i] * 4;
                cp_async16(sab + doff,             g_Kh + koff);
                cp_async16(sab + 2304 * 4 + doff,  g_Kl + koff);
                cp_async16(sab + 4608 * 4 + doff,  g_Vth + vbs + voff);
                cp_async16(sab + 6912 * 4 + doff,  g_Vtl + vbs + voff);
            }
            CP_COMMIT();
            CP_WAIT1();
        } else {
            CP_WAIT0();
        }
        __syncthreads();

        float st[8][4];
        #pragma unroll
        for (int nt = 0; nt < 8; nt++)
            #pragma unroll
            for (int i = 0; i < 4; i++) st[nt][i] = 0.0f;

        #pragma unroll
        for (int kk = 0; kk < 4; kk++) {
            #pragma unroll
            for (int nt = 0; nt < 8; nt++) {
                uint32_t bb[4];
                ldsm4(bb, sab + (stp + (uint32_t)nt * 288u + kk * 8 + bofs) * 4);
                mma_f16(st[nt], qh[kk][0], qh[kk][1], qh[kk][2], qh[kk][3], bb[0], bb[1]);
                mma_f16(st[nt], qh[kk][0], qh[kk][1], qh[kk][2], qh[kk][3], bb[2], bb[3]);
            }
        }

        if (tt >= 2 * G) {
            #pragma unroll
            for (int nt = 0; nt < 8; nt++) {
                int c0 = tt * 64 + nt * 8 + 2 * tg;
                if (c0     > r0)     st[nt][0] = -1e30f;
                if (c0 + 1 > r0)     st[nt][1] = -1e30f;
                if (c0     > r0 + 8) st[nt][2] = -1e30f;
                if (c0 + 1 > r0 + 8) st[nt][3] = -1e30f;
            }
        }

        float mn0 = m0v, mn1 = m1v;
        #pragma unroll
        for (int nt = 0; nt < 8; nt++) {
            mn0 = fmaxf(mn0, fmaxf(st[nt][0], st[nt][1]));
            mn1 = fmaxf(mn1, fmaxf(st[nt][2], st[nt][3]));
        }
        mn0 = fmaxf(mn0, __shfl_xor_sync(0xffffffffu, mn0, 1));
        mn0 = fmaxf(mn0, __shfl_xor_sync(0xffffffffu, mn0, 2));
        mn1 = fmaxf(mn1, __shfl_xor_sync(0xffffffffu, mn1, 1));
        mn1 = fmaxf(mn1, __shfl_xor_sync(0xffffffffu, mn1, 2));
        const float a0 = __expf(m0v - mn0);
        const float a1 = __expf(m1v - mn1);
        m0v = mn0; m1v = mn1;
        float rs0 = 0.0f, rs1 = 0.0f;
        #pragma unroll
        for (int nt = 0; nt < 8; nt++) {
            st[nt][0] = __expf(st[nt][0] - mn0);
            st[nt][1] = __expf(st[nt][1] - mn0);
            st[nt][2] = __expf(st[nt][2] - mn1);
            st[nt][3] = __expf(st[nt][3] - mn1);
            rs0 += st[nt][0] + st[nt][1];
            rs1 += st[nt][2] + st[nt][3];
        }
        l0 = l0 * a0 + rs0;
        l1 = l1 * a1 + rs1;
        #pragma unroll
        for (int nt = 0; nt < 8; nt++) {
            o[nt][0] *= a0; o[nt][1] *= a0;
            o[nt][2] *= a1; o[nt][3] *= a1;
        }

        #pragma unroll
        for (int kk = 0; kk < 4; kk++) {
            uint32_t ph[4];
            ph[0] = packhf(st[2 * kk][0],     st[2 * kk][1]);
            ph[1] = packhf(st[2 * kk][2],     st[2 * kk][3]);
            ph[2] = packhf(st[2 * kk + 1][0], st[2 * kk + 1][1]);
            ph[3] = packhf(st[2 * kk + 1][2], st[2 * kk + 1][3]);
            #pragma unroll
            for (int nd = 0; nd < 8; nd++) {
                uint32_t vv[4];
                ldsm4(vv, sab + (stp + 4608u + (uint32_t)nd * 288u + kk * 8 + bofs) * 4);
                mma_f16(o[nd], ph[0], ph[1], ph[2], ph[3], vv[0], vv[1]);
                mma_f16(o[nd], ph[0], ph[1], ph[2], ph[3], vv[2], vv[3]);
            }
        }
        __syncthreads();
    }

    l0 += __shfl_xor_sync(0xffffffffu, l0, 1);
    l0 += __shfl_xor_sync(0xffffffffu, l0, 2);
    l1 += __shfl_xor_sync(0xffffffffu, l1, 1);
    l1 += __shfl_xor_sync(0xffffffffu, l1, 2);

    const int rr = w * 16 + gid;
    if (h == 0) {
        const float i0 = 1.0f / l0, i1 = 1.0f / l1;
        float* o0 = out + ((size_t)b * T_ + G * 128 + rr) * H_;
        float* o1 = out + ((size_t)b * T_ + G * 128 + rr + 8) * H_;
        #pragma unroll
        for (int nt = 0; nt < 8; nt++) {
            const int col = nt * 8 + 2 * tg;
            *(float2*)(o0 + col) = make_float2(o[nt][0] * i0, o[nt][1] * i0);
            *(float2*)(o1 + col) = make_float2(o[nt][2] * i1, o[nt][3] * i1);
        }
    } else {
        float* op0 = &g_Op[b][G][s][rr][0];
        float* op1 = &g_Op[b][G][s][rr + 8][0];
        #pragma unroll
        for (int nt = 0; nt < 8; nt++) {
            const int col = nt * 8 + 2 * tg;
            *(float2*)(op0 + col) = make_float2(o[nt][0], o[nt][1]);
            *(float2*)(op1 + col) = make_float2(o[nt][2], o[nt][3]);
        }
        if (tg == 0) {
            g_Ml[b][G][s][rr][0]     = m0v;
            g_Ml[b][G][s][rr][1]     = l0;
            g_Ml[b][G][s][rr + 8][0] = m1v;
            g_Ml[b][G][s][rr + 8][1] = l1;
        }
    }
}

// ---------------------------------------------------------------------------
// Kernel 3: combine split partials (G >= 4).  (unchanged)
// ---------------------------------------------------------------------------
__global__ __launch_bounds__(256) void attn_combine_kernel(float* __restrict__ out)
{
    const int G    = 4 + (blockIdx.x >> 1);
    const int half = blockIdx.x & 1;
    const int b    = blockIdx.y;
    const int tid  = threadIdx.x;
    const int r    = half * 64 + (tid >> 2);
    const int q4   = tid & 3;
    const int dbase = q4 * 16;
    const int ns   = G / 4 + 1;

    float mv[4], lv[4], wv[4];
    float M = -1e30f;
    for (int i = 0; i < ns; i++) {
        mv[i] = g_Ml[b][G][i][r][0];
        lv[i] = g_Ml[b][G][i][r][1];
        M = fmaxf(M, mv[i]);
    }
    float L = 0.0f;
    for (int i = 0; i < ns; i++) {
        wv[i] = __expf(mv[i] - M);
        L += wv[i] * lv[i];
    }
    const float invL = 1.0f / L;

    float acc[16];
    #pragma unroll
    for (int d = 0; d < 16; d++) acc[d] = 0.0f;

    for (int i = 0; i < ns; i++) {
        const float* op = &g_Op[b][G][i][r][dbase];
        const float wi = wv[i];
        #pragma unroll
        for (int d4 = 0; d4 < 4; d4++) {
            float4 v = *(const float4*)(op + d4 * 4);
            acc[d4 * 4 + 0] += wi * v.x;
            acc[d4 * 4 + 1] += wi * v.y;
            acc[d4 * 4 + 2] += wi * v.z;
            acc[d4 * 4 + 3] += wi * v.w;
        }
    }

    float* orow = out + ((size_t)b * T_ + G * 128 + r) * H_ + dbase;
    #pragma unroll
    for (int d4 = 0; d4 < 4; d4++) {
        float4 v;
        v.x = acc[d4 * 4 + 0] * invL;
        v.y = acc[d4 * 4 + 1] * invL;
        v.z = acc[d4 * 4 + 2] * invL;
        v.w = acc[d4 * 4 + 3] * invL;
        *(float4*)(orow + d4 * 4) = v;
    }
}

// ---------------------------------------------------------------------------
extern "C" void kernel_launch(void* const* d_in, const int* in_sizes, int n_in,
                              void* d_out, int out_size)
{
    const float* x  = (const float*)d_in[0];
    const float* Wq = (const float*)d_in[1];
    const float* bq = (const float*)d_in[2];
    const float* Wk = (const float*)d_in[3];
    const float* bk = (const float*)d_in[4];
    const float* Wv = (const float*)d_in[5];
    const float* bv = (const float*)d_in[6];
    float* out = (float*)d_out;

    cudaFuncSetAttribute(qkv_mma_kernel,
                         cudaFuncAttributeMaxDynamicSharedMemorySize, SMEM_DYN);
    cudaFuncSetAttribute(attn_split_kernel,
                         cudaFuncAttributeMaxDynamicSharedMemorySize, ATT_SMEM);

    wsplit_kernel<<<384, 256>>>(Wq, Wk, Wv);
    qkv_mma_kernel<<<128, 256, SMEM_DYN>>>(x, bq, bk, bv);
    vsplit_kernel<<<256, 256>>>();
    attn_split_kernel<<<dim3(40, B_), 256, ATT_SMEM>>>(out);
    attn_combine_kernel<<<dim3(24, B_), 256>>>(out);
}

// round 13
// speedup vs baseline: 1.1598x; 1.0534x over previous
#include <cuda_runtime.h>
#include <cuda_fp16.h>
#include <cstdint>

#define B_ 8
#define T_ 2048
#define D_ 1024
#define H_ 64
#define M_ (B_ * T_)        // 16384 rows

// ---------------------------------------------------------------------------
// Device scratch
// ---------------------------------------------------------------------------
__device__ float g_V[M_ * H_];                      // fp32 V (intermediate)
__device__ uint32_t g_Qh[M_ * 32];                  // packed fp16 Q (pre-scaled)
__device__ uint32_t g_Kh[M_ * 32], g_Kl[M_ * 32];   // packed fp16 hi/lo K
__device__ uint32_t g_Vth[256 * 64 * 32];           // V^T fp16 hi, [tile][dim][keypair]
__device__ uint32_t g_Vtl[256 * 64 * 32];           // V^T fp16 lo

// W transposed, fp16 hi/lo split, packed 2-per-u32 along k
__device__ uint32_t g_Whl[6][64][512];

// Split-KV partials: [b][G(128-row block)][split][row][dim]
__device__ float g_Op[B_][16][4][128][H_];
__device__ float g_Ml[B_][16][4][128][2];

// ---------------------------------------------------------------------------
// Helpers
// ---------------------------------------------------------------------------
__device__ __forceinline__ uint32_t smem_u32(const void* p) {
    uint32_t a;
    asm("{ .reg .u64 t; cvta.to.shared.u64 t, %1; cvt.u32.u64 %0, t; }" : "=r"(a) : "l"(p));
    return a;
}
__device__ __forceinline__ uint32_t packhf(float a, float b) {   // a->lo, b->hi
    __half2 h = __floats2half2_rn(a, b);
    return *reinterpret_cast<uint32_t*>(&h);
}
__device__ __forceinline__ float2 unpackhf(uint32_t p) {
    __half2 h = *reinterpret_cast<__half2*>(&p);
    return __half22float2(h);
}
__device__ __forceinline__ void mma_f16(float* c,
    uint32_t a0, uint32_t a1, uint32_t a2, uint32_t a3, uint32_t b0, uint32_t b1)
{
    asm volatile("mma.sync.aligned.m16n8k16.row.col.f32.f16.f16.f32 "
        "{%0,%1,%2,%3}, {%4,%5,%6,%7}, {%8,%9}, {%0,%1,%2,%3};"
        : "+f"(c[0]), "+f"(c[1]), "+f"(c[2]), "+f"(c[3])
        : "r"(a0), "r"(a1), "r"(a2), "r"(a3), "r"(b0), "r"(b1));
}
__device__ __forceinline__ void ldsm4(uint32_t* r, uint32_t byte_addr) {
    asm volatile("ldmatrix.sync.aligned.m8n8.x4.shared.b16 {%0,%1,%2,%3}, [%4];"
        : "=r"(r[0]), "=r"(r[1]), "=r"(r[2]), "=r"(r[3]) : "r"(byte_addr));
}
__device__ __forceinline__ void cp_async16(uint32_t dst, const void* src) {
    asm volatile("cp.async.cg.shared.global [%0], [%1], 16;" :: "r"(dst), "l"(src) : "memory");
}
#define CP_COMMIT()  asm volatile("cp.async.commit_group;" ::: "memory")
#define CP_WAIT1()   asm volatile("cp.async.wait_group 1;"  ::: "memory")
#define CP_WAIT0()   asm volatile("cp.async.wait_group 0;"  ::: "memory")

// ---------------------------------------------------------------------------
// Kernel 0: transpose + fp16 hi/lo split + pack of the three weight matrices.
// ---------------------------------------------------------------------------
__global__ __launch_bounds__(256) void wsplit_kernel(
    const float* __restrict__ Wq, const float* __restrict__ Wk, const float* __restrict__ Wv)
{
    int idx = blockIdx.x * 256 + threadIdx.x;
    int o  = idx >> 15;
    int n  = (idx >> 9) & 63;
    int kp = idx & 511;
    const float* W = (o == 0) ? Wq : (o == 1) ? Wk : Wv;
    float w0 = W[(2 * kp + 0) * 64 + n];
    float w1 = W[(2 * kp + 1) * 64 + n];
    uint32_t hp = packhf(w0, w1);
    float2 f = unpackhf(hp);
    g_Whl[o][n][kp]     = hp;
    g_Whl[3 + o][n][kp] = packhf(w0 - f.x, w1 - f.y);
}

// ---------------------------------------------------------------------------
// Kernel 1: fused QKV projection, mma.sync fp16, asymmetric 2-mma split.
// 768 threads = 24 warps: warp (j = w>>3, rowgrp = w&7) computes output j
// (Q/K/V) for 16 rows of the CTA's 128-row tile -> acc 32 regs/thread,
// 24 warps/SM.  x loaded/packed once per CTA by threads < 512; W cp.async'd
// by all threads (2 segs each).  Stage (u32): xs [128][20] @0, ws @2560.
// ---------------------------------------------------------------------------
#define STAGE_U   10240
#define SMEM_DYN  (2 * STAGE_U * 4)

__global__ __launch_bounds__(768, 1) void qkv_mma_kernel(
    const float* __restrict__ x,
    const float* __restrict__ bq, const float* __restrict__ bk, const float* __restrict__ bv)
{
    extern __shared__ uint32_t sm[];
    __shared__ float sbias[3][64];

    const int tid  = threadIdx.x;
    const int w    = tid >> 5;
    const int lane = tid & 31;
    const int gid  = lane >> 2;
    const int tg   = lane & 3;
    const int m0   = blockIdx.x * 128;
    const int j    = w >> 3;          // output: 0=Q 1=K 2=V
    const int rg   = w & 7;           // row group (16 rows)

    if (tid < 64) {
        sbias[0][tid] = bq[tid];
        sbias[1][tid] = bk[tid];
        sbias[2][tid] = bv[tid];
    }

    // x loaders: threads 0..511, 8 floats each (quarter row)
    const int xrow = tid >> 2;
    const int xq   = tid & 3;
    const float* xbase = x + (size_t)(m0 + xrow) * D_ + xq * 8;
    const bool xload = (tid < 512);

    // W loaders: 1536 16B-segments per chunk, 2 per thread
    uint32_t wdst[2];
    const uint32_t* wsrc[2];
    #pragma unroll
    for (int it = 0; it < 2; it++) {
        int sid = it * 768 + tid;                 // 0..1535
        int jw = sid >> 8, n = (sid >> 2) & 63, gq = sid & 3;
        wdst[it] = 2560u + (uint32_t)jw * 1280u + (uint32_t)n * 20u + (uint32_t)gq * 4u;
        wsrc[it] = &g_Whl[jw][n][gq * 4];
    }
    const uint32_t smbase = smem_u32(sm);

    // ldmatrix lane offsets (u32 units)
    const uint32_t aofs = (uint32_t)((rg * 16 + (lane & 7) + ((lane >> 3) & 1) * 8) * 20
                                     + (lane >> 4) * 4);
    const uint32_t bofs = (uint32_t)((lane & 7) * 20 + ((lane >> 3) & 1) * 4
                                     + (lane >> 4) * 3840);

    float acc[8][4];
    #pragma unroll
    for (int nt = 0; nt < 8; nt++)
        #pragma unroll
        for (int i = 0; i < 4; i++) acc[nt][i] = 0.0f;

    #pragma unroll
    for (int it = 0; it < 2; it++)
        cp_async16(smbase + wdst[it] * 4, wsrc[it]);
    CP_COMMIT();

    float4 xv[2][2];
    if (xload) {
        xv[0][0] = *(const float4*)(xbase + 0);
        xv[0][1] = *(const float4*)(xbase + 4);
    }

    #pragma unroll 2
    for (int s = 0; s < 32; s++) {
        const int p   = s & 1;
        const int np  = p ^ 1;
        const uint32_t st = (uint32_t)p * STAGE_U;

        if (s + 1 < 32) {
            #pragma unroll
            for (int it = 0; it < 2; it++)
                cp_async16(smbase + (np * STAGE_U + wdst[it]) * 4,
                           wsrc[it] + (size_t)(s + 1) * 16);
        }
        CP_COMMIT();
        if (xload && s + 1 < 32) {
            const float* xp = xbase + (s + 1) * 32;
            xv[np][0] = *(const float4*)(xp + 0);
            xv[np][1] = *(const float4*)(xp + 4);
        }

        // pack + STS x chunk: 8 floats -> 4 u32
        if (xload) {
            float4 v0 = xv[p][0], v1 = xv[p][1];
            uint4 hp;
            hp.x = packhf(v0.x, v0.y);
            hp.y = packhf(v0.z, v0.w);
            hp.z = packhf(v1.x, v1.y);
            hp.w = packhf(v1.z, v1.w);
            *(uint4*)&sm[st + (uint32_t)xrow * 20u + (uint32_t)xq * 4u] = hp;
        }

        CP_WAIT1();
        __syncthreads();

        #pragma unroll
        for (int kk = 0; kk < 2; kk++) {
            uint32_t a[4];
            ldsm4(a, smbase + (st + aofs + kk * 8) * 4);
            #pragma unroll
            for (int nt = 0; nt < 8; nt++) {
                uint32_t bb[4];
                ldsm4(bb, smbase + (st + 2560u + (uint32_t)j * 1280u
                                    + (uint32_t)nt * 160u + kk * 8 + bofs) * 4);
                mma_f16(acc[nt], a[0], a[1], a[2], a[3], bb[0], bb[1]);
                mma_f16(acc[nt], a[0], a[1], a[2], a[3], bb[2], bb[3]);
            }
        }
        __syncthreads();
    }

    // ---- epilogue: warp writes its output j for its 16 rows ----
    const int r0 = m0 + rg * 16 + gid;
    const float scale = (j == 0) ? 0.125f : 1.0f;
    #pragma unroll
    for (int nt = 0; nt < 8; nt++) {
        const int col = nt * 8 + 2 * tg;
        float v00 = (acc[nt][0] + sbias[j][col])     * scale;
        float v01 = (acc[nt][1] + sbias[j][col + 1]) * scale;
        float v10 = (acc[nt][2] + sbias[j][col])     * scale;
        float v11 = (acc[nt][3] + sbias[j][col + 1]) * scale;
        const int pi = nt * 4 + tg;
        if (j == 2) {
            *(float2*)(g_V + (size_t)r0 * H_ + col)       = make_float2(v00, v01);
            *(float2*)(g_V + (size_t)(r0 + 8) * H_ + col) = make_float2(v10, v11);
        } else if (j == 0) {
            g_Qh[(size_t)r0 * 32 + pi]       = packhf(v00, v01);
            g_Qh[(size_t)(r0 + 8) * 32 + pi] = packhf(v10, v11);
        } else {
            uint32_t h0 = packhf(v00, v01);
            uint32_t h1 = packhf(v10, v11);
            float2 f0 = unpackhf(h0), f1 = unpackhf(h1);
            g_Kh[(size_t)r0 * 32 + pi]       = h0;
            g_Kh[(size_t)(r0 + 8) * 32 + pi] = h1;
            g_Kl[(size_t)r0 * 32 + pi]       = packhf(v00 - f0.x, v01 - f0.y);
            g_Kl[(size_t)(r0 + 8) * 32 + pi] = packhf(v10 - f1.x, v11 - f1.y);
        }
    }
}

// ---------------------------------------------------------------------------
// Kernel 1b: V -> transposed fp16 hi/lo split [tile][dim][keypair].
// ---------------------------------------------------------------------------
__global__ __launch_bounds__(256) void vsplit_kernel()
{
    __shared__ float vs[64][65];
    const int bt  = blockIdx.x;
    const int tid = threadIdx.x;
    const float* base = g_V + (size_t)bt * 64 * 64;

    #pragma unroll
    for (int i = 0; i < 16; i++) {
        int id = i * 256 + tid;
        vs[id >> 6][id & 63] = base[id];
    }
    __syncthreads();

    const int d   = tid >> 2;
    const int kpb = (tid & 3) * 8;
    uint32_t* oh = g_Vth + (size_t)bt * 2048 + d * 32;
    uint32_t* ol = g_Vtl + (size_t)bt * 2048 + d * 32;
    #pragma unroll
    for (int jj = 0; jj < 8; jj++) {
        int kp = kpb + jj;
        float v0 = vs[2 * kp][d];
        float v1 = vs[2 * kp + 1][d];
        uint32_t hp = packhf(v0, v1);
        float2 f = unpackhf(hp);
        oh[kp] = hp;
        ol[kp] = packhf(v0 - f.x, v1 - f.y);
    }
}

// ---------------------------------------------------------------------------
// Kernel 2: split-KV causal flash attention (exact R10 version, scalar LDS).
// CTA = 128 q-rows (8 warps), double-buffered cp.async, 2 CTAs/SM.
// Stage layout (u32, stride 9216): KH @0, KL @2304, VH @4608, VL @6912.
// ---------------------------------------------------------------------------
#define ASTG 9216
#define ATT_SMEM (2 * ASTG * 4)

__global__ __launch_bounds__(256, 2) void attn_split_kernel(float* __restrict__ out)
{
    extern __shared__ uint32_t sa[];

    const int bxr = 39 - (int)blockIdx.x;   // heavy first (LPT)
    const int b   = blockIdx.y;

    int h = 0;
    if (bxr >= 4)  h = 1;
    if (bxr >= 12) h = 2;
    if (bxr >= 24) h = 3;
    const int rem = bxr - 2 * h * (h + 1);
    const int qi  = rem / (h + 1);
    const int s   = rem - qi * (h + 1);
    const int G   = 4 * h + qi;              // 128-row q-block 0..15

    const int tid  = threadIdx.x;
    const int w    = tid >> 5;
    const int lane = tid & 31;
    const int gid  = lane >> 2;
    const int tg   = lane & 3;
    const int r0   = G * 128 + w * 16 + gid;

    uint32_t qh[4][4];
    {
        const uint32_t* qhp = g_Qh + ((size_t)b * T_ + r0) * 32;
        #pragma unroll
        for (int kk = 0; kk < 4; kk++) {
            qh[kk][0] = qhp[kk * 8 + tg];
            qh[kk][1] = qhp[8 * 32 + kk * 8 + tg];
            qh[kk][2] = qhp[kk * 8 + tg + 4];
            qh[kk][3] = qhp[8 * 32 + kk * 8 + tg + 4];
        }
    }

    float o[8][4];
    #pragma unroll
    for (int nt = 0; nt < 8; nt++)
        #pragma unroll
        for (int i = 0; i < 4; i++) o[nt][i] = 0.0f;
    float m0v = -1e30f, m1v = -1e30f, l0 = 0.0f, l1 = 0.0f;

    const uint32_t sab = smem_u32(sa);
    int lrow[2], lgq[2];
    #pragma unroll
    for (int i = 0; i < 2; i++) {
        int c = i * 256 + tid;
        lrow[i] = c >> 3;
        lgq[i]  = c & 7;
    }

    const int t0 = s * 8;
    const int t1 = min(s * 8 + 8, 2 * G + 2);
    const int ntile = t1 - t0;

    {
        const size_t krow = (size_t)b * T_ + t0 * 64;
        const size_t vbs  = ((size_t)b * 32 + t0) * 2048;
        #pragma unroll
        for (int i = 0; i < 2; i++) {
            uint32_t doff = (uint32_t)(lrow[i] * 36 + lgq[i] * 4) * 4;
            uint32_t koff = (krow + lrow[i]) * 32 + lgq[i] * 4;
            uint32_t voff = lrow[i] * 32 + lgq[i] * 4;
            cp_async16(sab + doff,             g_Kh + koff);
            cp_async16(sab + 2304 * 4 + doff,  g_Kl + koff);
            cp_async16(sab + 4608 * 4 + doff,  g_Vth + vbs + voff);
            cp_async16(sab + 6912 * 4 + doff,  g_Vtl + vbs + voff);
        }
        CP_COMMIT();
    }

    for (int ti = 0; ti < ntile; ti++) {
        const int tt = t0 + ti;
        const int p  = ti & 1;
        const uint32_t stp = (uint32_t)p * ASTG;

        if (ti + 1 < ntile) {
            const uint32_t stn = (uint32_t)(p ^ 1) * ASTG * 4;
            const size_t krow = (size_t)b * T_ + (tt + 1) * 64;
            const size_t vbs  = ((size_t)b * 32 + (tt + 1)) * 2048;
            #pragma unroll
            for (int i = 0; i < 2; i++) {
                uint32_t doff = stn + (uint32_t)(lrow[i] * 36 + lgq[i] * 4) * 4;
                uint32_t koff = (krow + lrow[i]) * 32 + lgq[i] * 4;
                uint32_t voff = lrow[i] * 32 + lgq[i] * 4;
                cp_async16(sab + doff,             g_Kh + koff);
                cp_async16(sab + 2304 * 4 + doff,  g_Kl + koff);
                cp_async16(sab + 4608 * 4 + doff,  g_Vth + vbs + voff);
                cp_async16(sab + 6912 * 4 + doff,  g_Vtl + vbs + voff);
            }
            CP_COMMIT();
            CP_WAIT1();
        } else {
            CP_WAIT0();
        }
        __syncthreads();

        float st[8][4];
        #pragma unroll
        for (int nt = 0; nt < 8; nt++)
            #pragma unroll
            for (int i = 0; i < 4; i++) st[nt][i] = 0.0f;

        #pragma unroll
        for (int kk = 0; kk < 4; kk++) {
            #pragma unroll
            for (int nt = 0; nt < 8; nt++) {
                const uint32_t base = stp + (uint32_t)(nt * 8 + gid) * 36u + kk * 8 + tg;
                uint32_t bh0 = sa[base],        bh1 = sa[base + 4];
                uint32_t bl0 = sa[base + 2304], bl1 = sa[base + 2304 + 4];
                mma_f16(st[nt], qh[kk][0], qh[kk][1], qh[kk][2], qh[kk][3], bh0, bh1);
                mma_f16(st[nt], qh[kk][0], qh[kk][1], qh[kk][2], qh[kk][3], bl0, bl1);
            }
        }

        if (tt >= 2 * G) {
            #pragma unroll
            for (int nt = 0; nt < 8; nt++) {
                int c0 = tt * 64 + nt * 8 + 2 * tg;
                if (c0     > r0)     st[nt][0] = -1e30f;
                if (c0 + 1 > r0)     st[nt][1] = -1e30f;
                if (c0     > r0 + 8) st[nt][2] = -1e30f;
                if (c0 + 1 > r0 + 8) st[nt][3] = -1e30f;
            }
        }

        float mn0 = m0v, mn1 = m1v;
        #pragma unroll
        for (int nt = 0; nt < 8; nt++) {
            mn0 = fmaxf(mn0, fmaxf(st[nt][0], st[nt][1]));
            mn1 = fmaxf(mn1, fmaxf(st[nt][2], st[nt][3]));
        }
        mn0 = fmaxf(mn0, __shfl_xor_sync(0xffffffffu, mn0, 1));
        mn0 = fmaxf(mn0, __shfl_xor_sync(0xffffffffu, mn0, 2));
        mn1 = fmaxf(mn1, __shfl_xor_sync(0xffffffffu, mn1, 1));
        mn1 = fmaxf(mn1, __shfl_xor_sync(0xffffffffu, mn1, 2));
        const float a0 = __expf(m0v - mn0);
        const float a1 = __expf(m1v - mn1);
        m0v = mn0; m1v = mn1;
        float rs0 = 0.0f, rs1 = 0.0f;
        #pragma unroll
        for (int nt = 0; nt < 8; nt++) {
            st[nt][0] = __expf(st[nt][0] - mn0);
            st[nt][1] = __expf(st[nt][1] - mn0);
            st[nt][2] = __expf(st[nt][2] - mn1);
            st[nt][3] = __expf(st[nt][3] - mn1);
            rs0 += st[nt][0] + st[nt][1];
            rs1 += st[nt][2] + st[nt][3];
        }
        l0 = l0 * a0 + rs0;
        l1 = l1 * a1 + rs1;
        #pragma unroll
        for (int nt = 0; nt < 8; nt++) {
            o[nt][0] *= a0; o[nt][1] *= a0;
            o[nt][2] *= a1; o[nt][3] *= a1;
        }

        #pragma unroll
        for (int kk = 0; kk < 4; kk++) {
            uint32_t ph[4];
            ph[0] = packhf(st[2 * kk][0],     st[2 * kk][1]);
            ph[1] = packhf(st[2 * kk][2],     st[2 * kk][3]);
            ph[2] = packhf(st[2 * kk + 1][0], st[2 * kk + 1][1]);
            ph[3] = packhf(st[2 * kk + 1][2], st[2 * kk + 1][3]);
            #pragma unroll
            for (int nd = 0; nd < 8; nd++) {
                const uint32_t base = stp + 4608u + (uint32_t)(nd * 8 + gid) * 36u + kk * 8 + tg;
                uint32_t vh0 = sa[base],        vh1 = sa[base + 4];
                uint32_t vl0 = sa[base + 2304], vl1 = sa[base + 2304 + 4];
                mma_f16(o[nd], ph[0], ph[1], ph[2], ph[3], vh0, vh1);
                mma_f16(o[nd], ph[0], ph[1], ph[2], ph[3], vl0, vl1);
            }
        }
        __syncthreads();
    }

    l0 += __shfl_xor_sync(0xffffffffu, l0, 1);
    l0 += __shfl_xor_sync(0xffffffffu, l0, 2);
    l1 += __shfl_xor_sync(0xffffffffu, l1, 1);
    l1 += __shfl_xor_sync(0xffffffffu, l1, 2);

    const int rr = w * 16 + gid;
    if (h == 0) {
        const float i0 = 1.0f / l0, i1 = 1.0f / l1;
        float* o0 = out + ((size_t)b * T_ + G * 128 + rr) * H_;
        float* o1 = out + ((size_t)b * T_ + G * 128 + rr + 8) * H_;
        #pragma unroll
        for (int nt = 0; nt < 8; nt++) {
            const int col = nt * 8 + 2 * tg;
            *(float2*)(o0 + col) = make_float2(o[nt][0] * i0, o[nt][1] * i0);
            *(float2*)(o1 + col) = make_float2(o[nt][2] * i1, o[nt][3] * i1);
        }
    } else {
        float* op0 = &g_Op[b][G][s][rr][0];
        float* op1 = &g_Op[b][G][s][rr + 8][0];
        #pragma unroll
        for (int nt = 0; nt < 8; nt++) {
            const int col = nt * 8 + 2 * tg;
            *(float2*)(op0 + col) = make_float2(o[nt][0], o[nt][1]);
            *(float2*)(op1 + col) = make_float2(o[nt][2], o[nt][3]);
        }
        if (tg == 0) {
            g_Ml[b][G][s][rr][0]     = m0v;
            g_Ml[b][G][s][rr][1]     = l0;
            g_Ml[b][G][s][rr + 8][0] = m1v;
            g_Ml[b][G][s][rr + 8][1] = l1;
        }
    }
}

// ---------------------------------------------------------------------------
// Kernel 3: combine split partials (G >= 4).  (unchanged)
// ---------------------------------------------------------------------------
__global__ __launch_bounds__(256) void attn_combine_kernel(float* __restrict__ out)
{
    const int G    = 4 + (blockIdx.x >> 1);
    const int half = blockIdx.x & 1;
    const int b    = blockIdx.y;
    const int tid  = threadIdx.x;
    const int r    = half * 64 + (tid >> 2);
    const int q4   = tid & 3;
    const int dbase = q4 * 16;
    const int ns   = G / 4 + 1;

    float mv[4], lv[4], wv[4];
    float M = -1e30f;
    for (int i = 0; i < ns; i++) {
        mv[i] = g_Ml[b][G][i][r][0];
        lv[i] = g_Ml[b][G][i][r][1];
        M = fmaxf(M, mv[i]);
    }
    float L = 0.0f;
    for (int i = 0; i < ns; i++) {
        wv[i] = __expf(mv[i] - M);
        L += wv[i] * lv[i];
    }
    const float invL = 1.0f / L;

    float acc[16];
    #pragma unroll
    for (int d = 0; d < 16; d++) acc[d] = 0.0f;

    for (int i = 0; i < ns; i++) {
        const float* op = &g_Op[b][G][i][r][dbase];
        const float wi = wv[i];
        #pragma unroll
        for (int d4 = 0; d4 < 4; d4++) {
            float4 v = *(const float4*)(op + d4 * 4);
            acc[d4 * 4 + 0] += wi * v.x;
            acc[d4 * 4 + 1] += wi * v.y;
            acc[d4 * 4 + 2] += wi * v.z;
            acc[d4 * 4 + 3] += wi * v.w;
        }
    }

    float* orow = out + ((size_t)b * T_ + G * 128 + r) * H_ + dbase;
    #pragma unroll
    for (int d4 = 0; d4 < 4; d4++) {
        float4 v;
        v.x = acc[d4 * 4 + 0] * invL;
        v.y = acc[d4 * 4 + 1] * invL;
        v.z = acc[d4 * 4 + 2] * invL;
        v.w = acc[d4 * 4 + 3] * invL;
        *(float4*)(orow + d4 * 4) = v;
    }
}

// ---------------------------------------------------------------------------
extern "C" void kernel_launch(void* const* d_in, const int* in_sizes, int n_in,
                              void* d_out, int out_size)
{
    const float* x  = (const float*)d_in[0];
    const float* Wq = (const float*)d_in[1];
    const float* bq = (const float*)d_in[2];
    const float* Wk = (const float*)d_in[3];
    const float* bk = (const float*)d_in[4];
    const float* Wv = (const float*)d_in[5];
    const float* bv = (const float*)d_in[6];
    float* out = (float*)d_out;

    cudaFuncSetAttribute(qkv_mma_kernel,
                         cudaFuncAttributeMaxDynamicSharedMemorySize, SMEM_DYN);
    cudaFuncSetAttribute(attn_split_kernel,
                         cudaFuncAttributeMaxDynamicSharedMemorySize, ATT_SMEM);

    wsplit_kernel<<<384, 256>>>(Wq, Wk, Wv);
    qkv_mma_kernel<<<128, 768, SMEM_DYN>>>(x, bq, bk, bv);
    vsplit_kernel<<<256, 256>>>();
    attn_split_kernel<<<dim3(40, B_), 256, ATT_SMEM>>>(out);
    attn_combine_kernel<<<dim3(24, B_), 256>>>(out);
}